// round 1
// baseline (speedup 1.0000x reference)
#include <cuda_runtime.h>
#include <cuda_bf16.h>
#include <cstdint>

#define D_FEAT 128
#define TILE_ROWS 64
#define NTHREADS 256
// smem: W [128][128] + xtile [64][128], floats
#define SMEM_BYTES ((D_FEAT * D_FEAT + TILE_ROWS * D_FEAT) * 4)

// ---- Blackwell packed f32x2 helpers ----
__device__ __forceinline__ unsigned long long pack2(float lo, float hi) {
    unsigned long long r;
    asm("mov.b64 %0, {%1,%2};" : "=l"(r) : "f"(lo), "f"(hi));
    return r;
}
__device__ __forceinline__ void unpack2(unsigned long long v, float& lo, float& hi) {
    asm("mov.b64 {%0,%1}, %2;" : "=f"(lo), "=f"(hi) : "l"(v));
}
__device__ __forceinline__ void fma2(unsigned long long& d,
                                     unsigned long long a,
                                     unsigned long long b) {
    asm("fma.rn.f32x2 %0, %1, %2, %0;" : "+l"(d) : "l"(a), "l"(b));
}
__device__ __forceinline__ float f4get(const float4& v, int i) {
    // i is compile-time after unroll
    return (i == 0) ? v.x : (i == 1) ? v.y : (i == 2) ? v.z : v.w;
}

__global__ void __launch_bounds__(NTHREADS, 2)
ginconv_fused_kernel(const float* __restrict__ X,
                     const float* __restrict__ W,
                     const int* __restrict__ rowptr,
                     const int* __restrict__ colidx,
                     float* __restrict__ out,
                     int n_nodes) {
    extern __shared__ float smem[];
    float* sW = smem;                       // 128*128
    float* sX = smem + D_FEAT * D_FEAT;     // 64*128

    const int tid  = threadIdx.x;
    const int warp = tid >> 5;
    const int lane = tid & 31;
    const int row0 = blockIdx.x * TILE_ROWS;

    // ---- Load W into shared memory (vectorized) ----
    {
        const float4* W4  = reinterpret_cast<const float4*>(W);
        float4*       sW4 = reinterpret_cast<float4*>(sW);
#pragma unroll
        for (int i = tid; i < (D_FEAT * D_FEAT) / 4; i += NTHREADS)
            sW4[i] = W4[i];
    }

    // ---- Phase 1: aggregate 8 rows per warp ----
    // Each lane owns 4 consecutive features (float4); one warp-load = full 512B row.
    const float4* X4 = reinterpret_cast<const float4*>(X);
#pragma unroll 1
    for (int j = 0; j < 8; j++) {
        const int r = row0 + warp * 8 + j;
        float4 acc = make_float4(0.f, 0.f, 0.f, 0.f);
        if (r < n_nodes) {
            int e         = rowptr[r];
            const int end = rowptr[r + 1];
            // unroll by 4 for memory-level parallelism
            for (; e + 4 <= end; e += 4) {
                const int c0 = colidx[e + 0];
                const int c1 = colidx[e + 1];
                const int c2 = colidx[e + 2];
                const int c3 = colidx[e + 3];
                float4 v0 = X4[(size_t)c0 * 32 + lane];
                float4 v1 = X4[(size_t)c1 * 32 + lane];
                float4 v2 = X4[(size_t)c2 * 32 + lane];
                float4 v3 = X4[(size_t)c3 * 32 + lane];
                acc.x += (v0.x + v1.x) + (v2.x + v3.x);
                acc.y += (v0.y + v1.y) + (v2.y + v3.y);
                acc.z += (v0.z + v1.z) + (v2.z + v3.z);
                acc.w += (v0.w + v1.w) + (v2.w + v3.w);
            }
            for (; e < end; e++) {
                const int c = colidx[e];
                float4 v = X4[(size_t)c * 32 + lane];
                acc.x += v.x; acc.y += v.y; acc.z += v.z; acc.w += v.w;
            }
        }
        *reinterpret_cast<float4*>(&sX[(warp * 8 + j) * D_FEAT + lane * 4]) = acc;
    }
    __syncthreads();

    // ---- Phase 2: xtile[64][128] @ W[128][128] via packed f32x2 FMAs ----
    // Thread (ri, ci): rows ri*8..ri*8+7 (as 4 row-pairs), cols ci*4..ci*4+3.
    const int ri = tid >> 5;  // 0..7
    const int ci = tid & 31;  // 0..31

    unsigned long long acc2[4][4];
#pragma unroll
    for (int rp = 0; rp < 4; rp++)
#pragma unroll
        for (int c = 0; c < 4; c++) acc2[rp][c] = 0ULL;

    for (int k0 = 0; k0 < D_FEAT; k0 += 4) {
        // a-values: 8 rows, 4 consecutive k each (LDS.128 broadcast per row)
        float4 av[8];
#pragma unroll
        for (int j = 0; j < 8; j++)
            av[j] = *reinterpret_cast<const float4*>(&sX[(ri * 8 + j) * D_FEAT + k0]);

#pragma unroll
        for (int kk = 0; kk < 4; kk++) {
            const float4 b =
                *reinterpret_cast<const float4*>(&sW[(k0 + kk) * D_FEAT + ci * 4]);
            unsigned long long bb[4];
            bb[0] = pack2(b.x, b.x);
            bb[1] = pack2(b.y, b.y);
            bb[2] = pack2(b.z, b.z);
            bb[3] = pack2(b.w, b.w);
#pragma unroll
            for (int rp = 0; rp < 4; rp++) {
                const unsigned long long aa =
                    pack2(f4get(av[2 * rp], kk), f4get(av[2 * rp + 1], kk));
#pragma unroll
                for (int c = 0; c < 4; c++) fma2(acc2[rp][c], aa, bb[c]);
            }
        }
    }

    // ---- Store: unpack row-pairs, vectorized float4 per row ----
#pragma unroll
    for (int rp = 0; rp < 4; rp++) {
        float lo[4], hi[4];
#pragma unroll
        for (int c = 0; c < 4; c++) unpack2(acc2[rp][c], lo[c], hi[c]);
        const int r_lo = row0 + ri * 8 + rp * 2;
        const int r_hi = r_lo + 1;
        if (r_lo < n_nodes)
            *reinterpret_cast<float4*>(&out[(size_t)r_lo * D_FEAT + ci * 4]) =
                make_float4(lo[0], lo[1], lo[2], lo[3]);
        if (r_hi < n_nodes)
            *reinterpret_cast<float4*>(&out[(size_t)r_hi * D_FEAT + ci * 4]) =
                make_float4(hi[0], hi[1], hi[2], hi[3]);
    }
}

extern "C" void kernel_launch(void* const* d_in, const int* in_sizes, int n_in,
                              void* d_out, int out_size) {
    const float* X      = (const float*)d_in[0];
    const float* W      = (const float*)d_in[1];
    const int*   rowptr = (const int*)d_in[2];
    const int*   colidx = (const int*)d_in[3];
    float*       out    = (float*)d_out;

    const int n_nodes = in_sizes[2] - 1;  // row_pointers has N+1 entries

    cudaFuncSetAttribute(ginconv_fused_kernel,
                         cudaFuncAttributeMaxDynamicSharedMemorySize, SMEM_BYTES);

    const int grid = (n_nodes + TILE_ROWS - 1) / TILE_ROWS;
    ginconv_fused_kernel<<<grid, NTHREADS, SMEM_BYTES>>>(X, W, rowptr, colidx, out,
                                                         n_nodes);
}

// round 2
// speedup vs baseline: 1.1260x; 1.1260x over previous
#include <cuda_runtime.h>
#include <cstdint>

#define D 128
#define MAXN 100000

// Scratch for aggregated features X' = segment_sum(gather(X))
__device__ float g_Xp[(size_t)MAXN * D];

// ---- Blackwell packed f32x2 helpers ----
__device__ __forceinline__ unsigned long long pack2(float lo, float hi) {
    unsigned long long r;
    asm("mov.b64 %0, {%1,%2};" : "=l"(r) : "f"(lo), "f"(hi));
    return r;
}
__device__ __forceinline__ void unpack2(unsigned long long v, float& lo, float& hi) {
    asm("mov.b64 {%0,%1}, %2;" : "=f"(lo), "=f"(hi) : "l"(v));
}
__device__ __forceinline__ void fma2(unsigned long long& d,
                                     unsigned long long a,
                                     unsigned long long b) {
    asm("fma.rn.f32x2 %0, %1, %2, %0;" : "+l"(d) : "l"(a), "l"(b));
}

// ============================================================================
// Kernel 1: row aggregation. One warp per destination row; each lane owns 4
// consecutive features (float4) so one warp-load fetches a full 512B X row.
// No smem -> high occupancy -> enough MLP to saturate L2.
// ============================================================================
__global__ void __launch_bounds__(256)
agg_kernel(const float4* __restrict__ X4,
           const int* __restrict__ rowptr,
           const int* __restrict__ colidx,
           float4* __restrict__ Xp4,
           int n) {
    const int w    = (blockIdx.x * blockDim.x + threadIdx.x) >> 5;
    const int lane = threadIdx.x & 31;
    if (w >= n) return;

    int e         = rowptr[w];
    const int e1  = rowptr[w + 1];
    float4 acc = make_float4(0.f, 0.f, 0.f, 0.f);

    // 8-deep unroll: 8 outstanding 16B loads per lane (4KB/warp in flight)
    for (; e + 8 <= e1; e += 8) {
        float4 v[8];
#pragma unroll
        for (int i = 0; i < 8; i++)
            v[i] = X4[(size_t)colidx[e + i] * 32 + lane];
#pragma unroll
        for (int i = 0; i < 8; i++) {
            acc.x += v[i].x; acc.y += v[i].y;
            acc.z += v[i].z; acc.w += v[i].w;
        }
    }
    for (; e < e1; e++) {
        float4 v = X4[(size_t)colidx[e] * 32 + lane];
        acc.x += v.x; acc.y += v.y; acc.z += v.z; acc.w += v.w;
    }
    Xp4[(size_t)w * 32 + lane] = acc;
}

// ============================================================================
// Kernel 2: dense GEMM  out[n,128] = X'[n,128] @ W[128,128]  via packed f32x2.
// Block: 256 threads, 128-row x 128-col tile, thread tile 8x8.
// X' tile stored in smem PRE-DUPLICATED as (x,x) 64-bit pairs -> aa operand is
// a plain LDS.64. W rows read as natural 64-bit column pairs (ulonglong2 ->
// LDS.128). Zero packing MOVs in the hot loop.
// smem: sW 64KB + sXd 128KB = 192KB -> 1 block/SM (8 warps, enough for FFMA).
// ============================================================================
#define GT 256
#define GROWS 128
#define GEMM_SMEM (D * D * 4 + GROWS * D * 8)

__global__ void __launch_bounds__(GT, 1)
gemm_kernel(const float* __restrict__ Xp,
            const float* __restrict__ W,
            float* __restrict__ out,
            int n) {
    extern __shared__ unsigned char smem_raw[];
    float* sW = reinterpret_cast<float*>(smem_raw);                     // 64KB
    unsigned long long* sXd =
        reinterpret_cast<unsigned long long*>(smem_raw + D * D * 4);    // 128KB

    const int tid  = threadIdx.x;
    const int row0 = blockIdx.x * GROWS;

    // Load W (vectorized)
    {
        const float4* W4  = reinterpret_cast<const float4*>(W);
        float4*       sW4 = reinterpret_cast<float4*>(sW);
#pragma unroll
        for (int i = tid; i < (D * D) / 4; i += GT) sW4[i] = W4[i];
    }

    // Load X' tile, duplicating each element into a 64-bit (x,x) pair
    {
        const float4* Xp4 = reinterpret_cast<const float4*>(Xp);
#pragma unroll
        for (int i = tid; i < GROWS * (D / 4); i += GT) {
            const int row = i >> 5;   // i / 32
            const int c4  = i & 31;
            float4 v = make_float4(0.f, 0.f, 0.f, 0.f);
            const int gr = row0 + row;
            if (gr < n) v = Xp4[(size_t)gr * 32 + c4];
            unsigned long long* dst = &sXd[row * D + c4 * 4];
            dst[0] = pack2(v.x, v.x);
            dst[1] = pack2(v.y, v.y);
            dst[2] = pack2(v.z, v.z);
            dst[3] = pack2(v.w, v.w);
        }
    }
    __syncthreads();

    const int ri = tid >> 4;  // 0..15 : rows ri*8 .. ri*8+7
    const int ci = tid & 15;  // 0..15 : cols ci*8 .. ci*8+7

    unsigned long long acc[8][4];
#pragma unroll
    for (int j = 0; j < 8; j++)
#pragma unroll
        for (int c = 0; c < 4; c++) acc[j][c] = 0ULL;

    const unsigned long long* sW64 =
        reinterpret_cast<const unsigned long long*>(sW);  // [k][64 col-pairs]

    // Manually double-buffered k loop
    unsigned long long aa[2][8], bb[2][4];
#pragma unroll
    for (int j = 0; j < 8; j++) aa[0][j] = sXd[(ri * 8 + j) * D + 0];
    {
        ulonglong2 b01 = *reinterpret_cast<const ulonglong2*>(&sW64[ci * 4]);
        ulonglong2 b23 = *reinterpret_cast<const ulonglong2*>(&sW64[ci * 4 + 2]);
        bb[0][0] = b01.x; bb[0][1] = b01.y; bb[0][2] = b23.x; bb[0][3] = b23.y;
    }

#pragma unroll 4
    for (int k = 0; k < D; k++) {
        const int cur = k & 1;
        const int nxt = cur ^ 1;
        if (k + 1 < D) {
#pragma unroll
            for (int j = 0; j < 8; j++)
                aa[nxt][j] = sXd[(ri * 8 + j) * D + (k + 1)];
            ulonglong2 b01 = *reinterpret_cast<const ulonglong2*>(
                &sW64[(k + 1) * (D / 2) + ci * 4]);
            ulonglong2 b23 = *reinterpret_cast<const ulonglong2*>(
                &sW64[(k + 1) * (D / 2) + ci * 4 + 2]);
            bb[nxt][0] = b01.x; bb[nxt][1] = b01.y;
            bb[nxt][2] = b23.x; bb[nxt][3] = b23.y;
        }
#pragma unroll
        for (int j = 0; j < 8; j++)
#pragma unroll
            for (int c = 0; c < 4; c++) fma2(acc[j][c], aa[cur][j], bb[cur][c]);
    }

    // Store 8 rows x 8 cols per thread (two float4 per row)
#pragma unroll
    for (int j = 0; j < 8; j++) {
        const int row = row0 + ri * 8 + j;
        if (row >= n) continue;
        float lo0, hi0, lo1, hi1, lo2, hi2, lo3, hi3;
        unpack2(acc[j][0], lo0, hi0);
        unpack2(acc[j][1], lo1, hi1);
        unpack2(acc[j][2], lo2, hi2);
        unpack2(acc[j][3], lo3, hi3);
        float4* o = reinterpret_cast<float4*>(&out[(size_t)row * D + ci * 8]);
        o[0] = make_float4(lo0, hi0, lo1, hi1);
        o[1] = make_float4(lo2, hi2, lo3, hi3);
    }
}

extern "C" void kernel_launch(void* const* d_in, const int* in_sizes, int n_in,
                              void* d_out, int out_size) {
    const float* X      = (const float*)d_in[0];
    const float* W      = (const float*)d_in[1];
    const int*   rowptr = (const int*)d_in[2];
    const int*   colidx = (const int*)d_in[3];
    float*       out    = (float*)d_out;

    const int n = in_sizes[2] - 1;  // row_pointers has N+1 entries

    float* Xp;
    cudaGetSymbolAddress((void**)&Xp, g_Xp);

    // Kernel 1: aggregation (one warp per row)
    {
        const int total_threads = n * 32;
        const int grid = (total_threads + 255) / 256;
        agg_kernel<<<grid, 256>>>((const float4*)X, rowptr, colidx,
                                  (float4*)Xp, n);
    }

    // Kernel 2: GEMM
    {
        cudaFuncSetAttribute(gemm_kernel,
                             cudaFuncAttributeMaxDynamicSharedMemorySize,
                             GEMM_SMEM);
        const int grid = (n + GROWS - 1) / GROWS;
        gemm_kernel<<<grid, GT, GEMM_SMEM>>>(Xp, W, out, n);
    }
}

// round 3
// speedup vs baseline: 1.1766x; 1.0449x over previous
#include <cuda_runtime.h>
#include <cstdint>

#define D 128
#define MAXN 100000

// Scratch for aggregated features X' = segment_sum(gather(X))
__device__ float g_Xp[(size_t)MAXN * D];

// ---- Blackwell packed f32x2 helpers ----
__device__ __forceinline__ unsigned long long pack2(float lo, float hi) {
    unsigned long long r;
    asm("mov.b64 %0, {%1,%2};" : "=l"(r) : "f"(lo), "f"(hi));
    return r;
}
__device__ __forceinline__ void unpack2(unsigned long long v, float& lo, float& hi) {
    asm("mov.b64 {%0,%1}, %2;" : "=f"(lo), "=f"(hi) : "l"(v));
}
__device__ __forceinline__ void fma2(unsigned long long& d,
                                     unsigned long long a,
                                     unsigned long long b) {
    asm("fma.rn.f32x2 %0, %1, %2, %0;" : "+l"(d) : "l"(a), "l"(b));
}

// ============================================================================
// Kernel 1: row aggregation. One warp per destination row; each lane owns 4
// consecutive features (float4) so one warp-load fetches a full 512B X row.
// No smem -> high occupancy -> enough MLP to saturate L2.
// ============================================================================
__global__ void __launch_bounds__(256)
agg_kernel(const float4* __restrict__ X4,
           const int* __restrict__ rowptr,
           const int* __restrict__ colidx,
           float4* __restrict__ Xp4,
           int n) {
    const int w    = (blockIdx.x * blockDim.x + threadIdx.x) >> 5;
    const int lane = threadIdx.x & 31;
    if (w >= n) return;

    int e         = rowptr[w];
    const int e1  = rowptr[w + 1];
    float4 acc = make_float4(0.f, 0.f, 0.f, 0.f);

    for (; e + 8 <= e1; e += 8) {
        float4 v[8];
#pragma unroll
        for (int i = 0; i < 8; i++)
            v[i] = X4[(size_t)colidx[e + i] * 32 + lane];
#pragma unroll
        for (int i = 0; i < 8; i++) {
            acc.x += v[i].x; acc.y += v[i].y;
            acc.z += v[i].z; acc.w += v[i].w;
        }
    }
    for (; e < e1; e++) {
        float4 v = X4[(size_t)colidx[e] * 32 + lane];
        acc.x += v.x; acc.y += v.y; acc.z += v.z; acc.w += v.w;
    }
    Xp4[(size_t)w * 32 + lane] = acc;
}

// ============================================================================
// Kernel 2: dense GEMM  out[n,128] = X'[n,128] @ W[128,128]  via packed f32x2.
// 256 threads, 128x128 tile, 8x8 per thread. k stepped by 2 so EVERY smem
// access is an LDS.128: aa = duplicated (x,x) pairs for (k,k+1) in one 16B
// load; bb = two natural W column-pairs per 16B load. This halves the smem
// wavefront count vs R2 (which was L1-bound at 73%).
// ============================================================================
#define GT 256
#define GROWS 128
#define GEMM_SMEM (D * D * 4 + GROWS * D * 8)   // sW 64KB + sXd 128KB

__global__ void __launch_bounds__(GT, 1)
gemm_kernel(const float* __restrict__ Xp,
            const float* __restrict__ W,
            float* __restrict__ out,
            int n) {
    extern __shared__ unsigned char smem_raw[];
    float* sW = reinterpret_cast<float*>(smem_raw);                     // 64KB
    unsigned long long* sXd =
        reinterpret_cast<unsigned long long*>(smem_raw + D * D * 4);    // 128KB

    const int tid  = threadIdx.x;
    const int row0 = blockIdx.x * GROWS;

    // Load W (vectorized)
    {
        const float4* W4  = reinterpret_cast<const float4*>(W);
        float4*       sW4 = reinterpret_cast<float4*>(sW);
#pragma unroll
        for (int i = tid; i < (D * D) / 4; i += GT) sW4[i] = W4[i];
    }

    // Load X' tile, duplicating each element into a 64-bit (x,x) pair
    {
        const float4* Xp4 = reinterpret_cast<const float4*>(Xp);
#pragma unroll
        for (int i = tid; i < GROWS * (D / 4); i += GT) {
            const int row = i >> 5;   // i / 32
            const int c4  = i & 31;
            float4 v = make_float4(0.f, 0.f, 0.f, 0.f);
            const int gr = row0 + row;
            if (gr < n) v = Xp4[(size_t)gr * 32 + c4];
            unsigned long long* dst = &sXd[row * D + c4 * 4];
            dst[0] = pack2(v.x, v.x);
            dst[1] = pack2(v.y, v.y);
            dst[2] = pack2(v.z, v.z);
            dst[3] = pack2(v.w, v.w);
        }
    }
    __syncthreads();

    const int ri = tid >> 4;  // 0..15 : rows ri*8 .. ri*8+7
    const int ci = tid & 15;  // 0..15 : cols ci*8 .. ci*8+7

    unsigned long long acc[8][4];
#pragma unroll
    for (int j = 0; j < 8; j++)
#pragma unroll
        for (int c = 0; c < 4; c++) acc[j][c] = 0ULL;

    const ulonglong2* sXd2 = reinterpret_cast<const ulonglong2*>(sXd);
    const ulonglong2* sW2  = reinterpret_cast<const ulonglong2*>(sW);
    // sXd2: [row][k-pair]  stride D/2 per row
    // sW2 : [k][32 x (2 col-pairs)] stride D/4 per k

#pragma unroll 2
    for (int k0 = 0; k0 < D; k0 += 2) {
        // aa: 8 rows x 2 ks, one LDS.128 per row
        ulonglong2 a2[8];
#pragma unroll
        for (int j = 0; j < 8; j++)
            a2[j] = sXd2[(ri * 8 + j) * (D / 2) + (k0 >> 1)];

        // bb: 4 col-pairs for k0 and k0+1, two LDS.128 each
        const ulonglong2 b0a = sW2[k0 * (D / 4) + ci * 2];
        const ulonglong2 b0b = sW2[k0 * (D / 4) + ci * 2 + 1];
        const ulonglong2 b1a = sW2[(k0 + 1) * (D / 4) + ci * 2];
        const ulonglong2 b1b = sW2[(k0 + 1) * (D / 4) + ci * 2 + 1];

#pragma unroll
        for (int j = 0; j < 8; j++) {
            fma2(acc[j][0], a2[j].x, b0a.x);
            fma2(acc[j][1], a2[j].x, b0a.y);
            fma2(acc[j][2], a2[j].x, b0b.x);
            fma2(acc[j][3], a2[j].x, b0b.y);
            fma2(acc[j][0], a2[j].y, b1a.x);
            fma2(acc[j][1], a2[j].y, b1a.y);
            fma2(acc[j][2], a2[j].y, b1b.x);
            fma2(acc[j][3], a2[j].y, b1b.y);
        }
    }

    // Store 8 rows x 8 cols per thread (two float4 per row)
#pragma unroll
    for (int j = 0; j < 8; j++) {
        const int row = row0 + ri * 8 + j;
        if (row >= n) continue;
        float lo0, hi0, lo1, hi1, lo2, hi2, lo3, hi3;
        unpack2(acc[j][0], lo0, hi0);
        unpack2(acc[j][1], lo1, hi1);
        unpack2(acc[j][2], lo2, hi2);
        unpack2(acc[j][3], lo3, hi3);
        float4* o = reinterpret_cast<float4*>(&out[(size_t)row * D + ci * 8]);
        o[0] = make_float4(lo0, hi0, lo1, hi1);
        o[1] = make_float4(lo2, hi2, lo3, hi3);
    }
}

extern "C" void kernel_launch(void* const* d_in, const int* in_sizes, int n_in,
                              void* d_out, int out_size) {
    const float* X      = (const float*)d_in[0];
    const float* W      = (const float*)d_in[1];
    const int*   rowptr = (const int*)d_in[2];
    const int*   colidx = (const int*)d_in[3];
    float*       out    = (float*)d_out;

    const int n = in_sizes[2] - 1;  // row_pointers has N+1 entries

    float* Xp;
    cudaGetSymbolAddress((void**)&Xp, g_Xp);

    // Kernel 1: aggregation (one warp per row)
    {
        const int total_threads = n * 32;
        const int grid = (total_threads + 255) / 256;
        agg_kernel<<<grid, 256>>>((const float4*)X, rowptr, colidx,
                                  (float4*)Xp, n);
    }

    // Kernel 2: GEMM
    {
        cudaFuncSetAttribute(gemm_kernel,
                             cudaFuncAttributeMaxDynamicSharedMemorySize,
                             GEMM_SMEM);
        const int grid = (n + GROWS - 1) / GROWS;
        gemm_kernel<<<grid, GT, GEMM_SMEM>>>(Xp, W, out, n);
    }
}